// round 12
// baseline (speedup 1.0000x reference)
#include <cuda_runtime.h>

// MyLSTM: 2-layer LSTM (INP=3, H=4) + per-timestep MLP head.
// Systolic split: 8 threads per sequence. Lanes 0-3 (low quad) run layer 0,
// lanes 4-7 (high quad) run layer 1 + head, skewed one timestep behind.
// Both roles execute the IDENTICAL instruction stream (8-wide dot, same gate
// math) with different register-resident weights -> no warp divergence.
// One width-8 shuffle round per step exchanges h0 and h1.
// tanh.approx.f32 activations; sigmoid via tanh identity (pre-halved weights).

#define BATCH 4096
#define SEQT  1024

__device__ __forceinline__ float tanh_fast(float x) {
    float r;
    asm("tanh.approx.f32 %0, %1;" : "=f"(r) : "f"(x));
    return r;
}

// expects pre-activation already multiplied by 0.5 (weights pre-halved)
__device__ __forceinline__ float sigmoid_half(float xh) {
    return fmaf(0.5f, tanh_fast(xh), 0.5f);
}

extern "C" __global__ void __launch_bounds__(128, 1)
lstm_mlp_kernel(const float* __restrict__ x,
                const float* __restrict__ Wih0, const float* __restrict__ Whh0,
                const float* __restrict__ bih0, const float* __restrict__ bhh0,
                const float* __restrict__ Wih1, const float* __restrict__ Whh1,
                const float* __restrict__ bih1, const float* __restrict__ bhh1,
                const float* __restrict__ W1,   const float* __restrict__ b1,
                const float* __restrict__ W2,   const float* __restrict__ b2,
                float* __restrict__ y)
{
    const int tid  = blockIdx.x * 128 + threadIdx.x;
    const int seq  = tid >> 3;          // sequence index (8 lanes per seq)
    const int role = (tid >> 2) & 1;    // 0 = layer0 quad, 1 = layer1 quad
    const int j    = tid & 3;           // hidden unit handled by this lane
    if (seq >= BATCH) return;

    // ---- unified 8-wide weights; gates i(0),f(1),o(3) pre-halved ----
    // low  (role 0): in = [x0,x1,x2,(0),  h0[0..3]]  -> w[3] = 0
    // high (role 1): in = [h0[0..3],      h1[0..3]]
    float w[4][8], wb[4];
    if (role == 0) {
#pragma unroll
        for (int g = 0; g < 4; ++g) {
            const float sc = (g == 2) ? 1.0f : 0.5f;
            const int r = g * 4 + j;
#pragma unroll
            for (int k = 0; k < 3; ++k) w[g][k] = sc * Wih0[r * 3 + k];
            w[g][3] = 0.0f;
#pragma unroll
            for (int k = 0; k < 4; ++k) w[g][4 + k] = sc * Whh0[r * 4 + k];
            wb[g] = sc * (bih0[r] + bhh0[r]);
        }
    } else {
#pragma unroll
        for (int g = 0; g < 4; ++g) {
            const float sc = (g == 2) ? 1.0f : 0.5f;
            const int r = g * 4 + j;
#pragma unroll
            for (int k = 0; k < 4; ++k) w[g][k]     = sc * Wih1[r * 4 + k];
#pragma unroll
            for (int k = 0; k < 4; ++k) w[g][4 + k] = sc * Whh1[r * 4 + k];
            wb[g] = sc * (bih1[r] + bhh1[r]);
        }
    }
    // MLP head weights in every lane (computed redundantly, uniform stream)
    float w1m[4][4], b1v[4], w2v[4];
#pragma unroll
    for (int k = 0; k < 4; ++k) {
#pragma unroll
        for (int m = 0; m < 4; ++m) w1m[k][m] = W1[k * 4 + m];
        b1v[k] = b1[k];
        w2v[k] = W2[k];
    }
    const float b2v = b2[0];

    // ---- state ----
    float h = 0.0f, c = 0.0f;           // own unit: h0_j (low) / h1_j (high)
    float m0 = 0, m1 = 0, m2 = 0, m3 = 0;  // broadcast h0[t-1]
    float n0 = 0, n1 = 0, n2 = 0, n3 = 0;  // broadcast h1[t-2]

    const float* xp = x + (size_t)seq * SEQT * 3;
    float*       yp = y + (size_t)seq * SEQT;

    const unsigned FULL = 0xFFFFFFFFu;
    const bool hi = (role != 0);
    const bool writer = (role == 1) && (j == 0);

    float x0 = xp[0], x1 = xp[1], x2 = xp[2];

#pragma unroll 2
    for (int t = 0; t <= SEQT; ++t) {
        // ---- build unified 8-wide input vector (SELs, no branches) ----
        const float in0 = hi ? m0 : x0;
        const float in1 = hi ? m1 : x1;
        const float in2 = hi ? m2 : x2;
        const float in3 = m3;               // low lane has w[g][3] = 0
        const float in4 = hi ? n0 : m0;
        const float in5 = hi ? n1 : m1;
        const float in6 = hi ? n2 : m2;
        const float in7 = hi ? n3 : m3;

        // ---- gate pre-activations: balanced-tree 8-wide dots ----
        float pre[4];
#pragma unroll
        for (int g = 0; g < 4; ++g) {
            float a0 = fmaf(w[g][1], in1, w[g][0] * in0);
            float a1 = fmaf(w[g][3], in3, w[g][2] * in2);
            float a2 = fmaf(w[g][5], in5, w[g][4] * in4);
            float a3 = fmaf(w[g][7], in7, fmaf(w[g][6], in6, wb[g]));
            pre[g] = (a0 + a1) + (a2 + a3);
        }

        // prefetch next x (only low lanes consume it; predicated loads)
        if (!hi && t + 1 < SEQT) {
            x0 = xp[3 * t + 3];
            x1 = xp[3 * t + 4];
            x2 = xp[3 * t + 5];
        }

        // ---- LSTM cell (identical for both roles) ----
        {
            const float ig = sigmoid_half(pre[0]);
            const float fg = sigmoid_half(pre[1]);
            const float gg = tanh_fast(pre[2]);
            const float og = sigmoid_half(pre[3]);
            c = fmaf(fg, c, ig * gg);
            h = og * tanh_fast(c);
        }
        // skew initial condition: layer1's first output is h1[-1] = 0
        if (t == 0 && hi) { h = 0.0f; c = 0.0f; }

        // ---- exchange: m = h0 (lanes 0-3), n = h1 (lanes 4-7) ----
        m0 = __shfl_sync(FULL, h, 0, 8);
        m1 = __shfl_sync(FULL, h, 1, 8);
        m2 = __shfl_sync(FULL, h, 2, 8);
        m3 = __shfl_sync(FULL, h, 3, 8);
        n0 = __shfl_sync(FULL, h, 4, 8);
        n1 = __shfl_sync(FULL, h, 5, 8);
        n2 = __shfl_sync(FULL, h, 6, 8);
        n3 = __shfl_sync(FULL, h, 7, 8);

        // ---- MLP head on h1[t-1] = n[0..3]; store y[t-1] ----
        if (t >= 1) {
            float acc = b2v;
#pragma unroll
            for (int k = 0; k < 4; ++k) {
                float s = b1v[k];
                s = fmaf(w1m[k][0], n0, s);
                s = fmaf(w1m[k][1], n1, s);
                s = fmaf(w1m[k][2], n2, s);
                s = fmaf(w1m[k][3], n3, s);
                acc = fmaf(w2v[k], tanh_fast(s), acc);
            }
            if (writer) yp[t - 1] = acc;
        }
    }
}

extern "C" void kernel_launch(void* const* d_in, const int* in_sizes, int n_in,
                              void* d_out, int out_size)
{
    const float* x    = (const float*)d_in[0];
    const float* Wih0 = (const float*)d_in[1];
    const float* Whh0 = (const float*)d_in[2];
    const float* bih0 = (const float*)d_in[3];
    const float* bhh0 = (const float*)d_in[4];
    const float* Wih1 = (const float*)d_in[5];
    const float* Whh1 = (const float*)d_in[6];
    const float* bih1 = (const float*)d_in[7];
    const float* bhh1 = (const float*)d_in[8];
    const float* W1   = (const float*)d_in[9];
    const float* b1   = (const float*)d_in[10];
    const float* W2   = (const float*)d_in[11];
    const float* b2   = (const float*)d_in[12];
    float* y = (float*)d_out;

    const int threads = 128;
    const int total   = BATCH * 8;          // 8 threads per sequence
    const int blocks  = (total + threads - 1) / threads;  // 256
    lstm_mlp_kernel<<<blocks, threads>>>(x, Wih0, Whh0, bih0, bhh0,
                                         Wih1, Whh1, bih1, bhh1,
                                         W1, b1, W2, b2, y);
}